// round 5
// baseline (speedup 1.0000x reference)
#include <cuda_runtime.h>

#define B_TOTAL 32768
#define D   256
#define H1  512
#define H2  256
#define E   16
#define O   64
#define BT  32
#define THREADS 512
#define XPAD 36   // padded row stride (floats)

// SMEM layout (floats):
//   x_t   [D][XPAD], h1t [H1][XPAD], h2t [H2][XPAD], gates [BT][E]
#define SMEM_FLOATS (D*XPAD + H1*XPAD + H2*XPAD + BT*E)

typedef unsigned long long u64;

__device__ __forceinline__ u64 f2_dup(float v) {
    u64 r; asm("mov.b64 %0, {%1, %1};" : "=l"(r) : "f"(v)); return r;
}
__device__ __forceinline__ void f2_fma(u64& d, u64 a, u64 b) {
    asm("fma.rn.f32x2 %0, %1, %2, %0;" : "+l"(d) : "l"(a), "l"(b));
}
__device__ __forceinline__ void f2_unpack(u64 v, float& lo, float& hi) {
    asm("mov.b64 {%0, %1}, %2;" : "=f"(lo), "=f"(hi) : "l"(v));
}

__global__ __launch_bounds__(THREADS, 1)
void moe_yts_fused_kernel(const float* __restrict__ x,
                          const float* __restrict__ gate_w,
                          const float* __restrict__ gate_b,
                          const float* __restrict__ W1,
                          const float* __restrict__ b1,
                          const float* __restrict__ W2,
                          const float* __restrict__ b2,
                          const float* __restrict__ W3,
                          const float* __restrict__ b3,
                          const float* __restrict__ head_w,
                          const float* __restrict__ head_b,
                          float* __restrict__ out)
{
    extern __shared__ float smem[];
    float* x_t     = smem;                  // [D][XPAD]
    float* h1t     = x_t + D * XPAD;        // [H1][XPAD]
    float* h2t     = h1t + H1 * XPAD;       // [H2][XPAD]
    float* gates_s = h2t + H2 * XPAD;       // [BT][E]

    const int t      = threadIdx.x;
    const int b_base = blockIdx.x * BT;

    // ---- Load x tile [BT, D] transposed into SMEM ----
    for (int idx = t; idx < BT * (D / 4); idx += THREADS) {
        int row = idx >> 6;
        int c4  = idx & 63;
        float4 v = *(const float4*)(x + (size_t)(b_base + row) * D + c4 * 4);
        x_t[(c4 * 4 + 0) * XPAD + row] = v.x;
        x_t[(c4 * 4 + 1) * XPAD + row] = v.y;
        x_t[(c4 * 4 + 2) * XPAD + row] = v.z;
        x_t[(c4 * 4 + 3) * XPAD + row] = v.w;
    }
    __syncthreads();

    // ---- Gate logits ----
    {
        int b = t >> 4;
        int e = t & 15;
        float acc = gate_b[e];
        #pragma unroll 8
        for (int d = 0; d < D; d++)
            acc = fmaf(x_t[d * XPAD + b], gate_w[d * E + e], acc);
        gates_s[b * E + e] = acc;
    }
    __syncthreads();
    if (t < BT) {
        float* row = gates_s + t * E;
        float m = row[0];
        #pragma unroll
        for (int e = 1; e < E; e++) m = fmaxf(m, row[e]);
        float s = 0.f;
        #pragma unroll
        for (int e = 0; e < E; e++) { float v = expf(row[e] - m); row[e] = v; s += v; }
        float inv = 1.0f / s;
        #pragma unroll
        for (int e = 0; e < E; e++) row[e] *= inv;
    }
    __syncthreads();

    // ---- Thread roles ----
    // GEMM1: 128 h-groups (4 h) x 4 b-groups (8 b = 4 native pairs)
    const int hgA = t & 127, bgA = t >> 7;
    const int hA0 = hgA * 4, bA0 = bgA * 8;
    // GEMM2: 128 k-groups (2 k) x 4 b-groups (8 b = 4 native pairs)
    const int kgB = t & 127, bgB = t >> 7;
    const int kB0 = kgB * 2, bB0 = bgB * 8;
    // GEMM3: 16 o-groups (4 o = 2 native w-pairs) x 32 b-rows
    const int og  = t & 15,  bC  = t >> 4;
    const int o0  = og * 4;

    float fused[4] = {0.f, 0.f, 0.f, 0.f};

    for (int e = 0; e < E; e++) {
        // ===== GEMM1: h1 = relu(x @ W1[e] + b1[e]) =====
        // acc[i = 4 b-pairs][j = 4 h]; x pairs native from LDS.128; dup weights.
        {
            u64 acc[4][4];
            #pragma unroll
            for (int i = 0; i < 4; i++)
                #pragma unroll
                for (int j = 0; j < 4; j++) acc[i][j] = 0ull;

            const float* w1p = W1 + (size_t)e * D * H1 + hA0;
            #pragma unroll 4
            for (int d = 0; d < D; d++) {
                const ulonglong2* xp = (const ulonglong2*)(x_t + d * XPAD + bA0);
                ulonglong2 xa = xp[0], xb = xp[1];
                u64 xi[4] = {xa.x, xa.y, xb.x, xb.y};
                float4 w = *(const float4*)(w1p + (size_t)d * H1);
                u64 wd[4] = {f2_dup(w.x), f2_dup(w.y), f2_dup(w.z), f2_dup(w.w)};
                #pragma unroll
                for (int j = 0; j < 4; j++)
                    #pragma unroll
                    for (int i = 0; i < 4; i++)
                        f2_fma(acc[i][j], xi[i], wd[j]);
            }
            float4 bb = *(const float4*)(b1 + e * H1 + hA0);
            float bj[4] = {bb.x, bb.y, bb.z, bb.w};
            #pragma unroll
            for (int j = 0; j < 4; j++) {
                float* dst = h1t + (hA0 + j) * XPAD + bA0;
                #pragma unroll
                for (int i = 0; i < 4; i++) {
                    float vlo, vhi;
                    f2_unpack(acc[i][j], vlo, vhi);
                    float2 st = make_float2(fmaxf(vlo + bj[j], 0.f),
                                            fmaxf(vhi + bj[j], 0.f));
                    *(float2*)(dst + 2 * i) = st;
                }
            }
        }
        __syncthreads();

        // ===== GEMM2: h2 = relu(h1 @ W2[e] + b2[e]) =====
        // acc[i = 4 b-pairs][j = 2 k]; h1 pairs native; dup 2 weights (LDG.64).
        {
            u64 acc[4][2];
            #pragma unroll
            for (int i = 0; i < 4; i++) { acc[i][0] = 0ull; acc[i][1] = 0ull; }

            const float* w2p = W2 + (size_t)e * H1 * H2 + kB0;
            #pragma unroll 4
            for (int h = 0; h < H1; h++) {
                const ulonglong2* xp = (const ulonglong2*)(h1t + h * XPAD + bB0);
                ulonglong2 xa = xp[0], xb = xp[1];
                u64 xi[4] = {xa.x, xa.y, xb.x, xb.y};
                float2 w = *(const float2*)(w2p + (size_t)h * H2);
                u64 w0 = f2_dup(w.x), w1 = f2_dup(w.y);
                #pragma unroll
                for (int i = 0; i < 4; i++) {
                    f2_fma(acc[i][0], xi[i], w0);
                    f2_fma(acc[i][1], xi[i], w1);
                }
            }
            float2 bb = *(const float2*)(b2 + e * H2 + kB0);
            float bj[2] = {bb.x, bb.y};
            #pragma unroll
            for (int j = 0; j < 2; j++) {
                float* dst = h2t + (kB0 + j) * XPAD + bB0;
                #pragma unroll
                for (int i = 0; i < 4; i++) {
                    float vlo, vhi;
                    f2_unpack(acc[i][j], vlo, vhi);
                    float2 st = make_float2(fmaxf(vlo + bj[j], 0.f),
                                            fmaxf(vhi + bj[j], 0.f));
                    *(float2*)(dst + 2 * i) = st;
                }
            }
        }
        __syncthreads();

        // ===== GEMM3: eo = h2 @ W3[e] + b3; fused += g * eo =====
        // pack along o: native weight pairs from LDG.128, dup h scalar.
        {
            u64 a3[2] = {0ull, 0ull};
            const u64* w3p = (const u64*)(W3 + (size_t)e * H2 * O + o0);
            #pragma unroll 4
            for (int k = 0; k < H2; k++) {
                float hv = h2t[k * XPAD + bC];
                u64 hd = f2_dup(hv);
                ulonglong2 w = *(const ulonglong2*)(w3p + (size_t)k * (O / 2));
                f2_fma(a3[0], hd, w.x);
                f2_fma(a3[1], hd, w.y);
            }
            float4 bb = *(const float4*)(b3 + e * O + o0);
            float g = gates_s[bC * E + e];
            float v0, v1, v2, v3;
            f2_unpack(a3[0], v0, v1);
            f2_unpack(a3[1], v2, v3);
            fused[0] = fmaf(g, v0 + bb.x, fused[0]);
            fused[1] = fmaf(g, v1 + bb.y, fused[1]);
            fused[2] = fmaf(g, v2 + bb.z, fused[2]);
            fused[3] = fmaf(g, v3 + bb.w, fused[3]);
        }
        __syncthreads();
    }

    // ---- Head ----
    {
        float4 hw = *(const float4*)(head_w + o0);
        float p = fused[0] * hw.x + fused[1] * hw.y + fused[2] * hw.z + fused[3] * hw.w;
        #pragma unroll
        for (int off = 8; off >= 1; off >>= 1)
            p += __shfl_xor_sync(0xffffffffu, p, off);
        if (og == 0)
            out[b_base + bC] = p + head_b[0];
    }
}

extern "C" void kernel_launch(void* const* d_in, const int* in_sizes, int n_in,
                              void* d_out, int out_size) {
    const float* x      = (const float*)d_in[0];
    const float* gate_w = (const float*)d_in[1];
    const float* gate_b = (const float*)d_in[2];
    const float* W1     = (const float*)d_in[3];
    const float* b1     = (const float*)d_in[4];
    const float* W2     = (const float*)d_in[5];
    const float* b2     = (const float*)d_in[6];
    const float* W3     = (const float*)d_in[7];
    const float* b3     = (const float*)d_in[8];
    const float* head_w = (const float*)d_in[9];
    const float* head_b = (const float*)d_in[10];
    float* out = (float*)d_out;

    const size_t smem_bytes = (size_t)SMEM_FLOATS * sizeof(float); // 149504 B
    cudaFuncSetAttribute(moe_yts_fused_kernel,
                         cudaFuncAttributeMaxDynamicSharedMemorySize,
                         (int)smem_bytes);

    moe_yts_fused_kernel<<<B_TOTAL / BT, THREADS, smem_bytes>>>(
        x, gate_w, gate_b, W1, b1, W2, b2, W3, b3, head_w, head_b, out);
}

// round 7
// speedup vs baseline: 3.1101x; 3.1101x over previous
#include <cuda_runtime.h>
#include <cuda_bf16.h>
#include <cstdint>

typedef uint32_t u32;
typedef uint64_t u64;

#define D_  256
#define H1_ 512
#define H2_ 256
#define E_  16
#define O_  64
#define B_  32768
#define MT  64          // batch rows per CTA
#define NT  256         // threads

// ---------- fragment-packed weight buffers ----------
// layout: [e][kt][nt][part(hi,lo)][lane(32)][word(2)] u32
__device__ u32 g_w1p[16u * 16 * 64 * 2 * 32 * 2];   // 2,097,152 u32
__device__ u32 g_w2p[16u * 32 * 32 * 2 * 32 * 2];   // 2,097,152 u32
__device__ u32 g_w3p[16u * 16 * 8 * 2 * 32 * 2];    //   262,144 u32

// ---------- SMEM (bytes) ----------
#define SM_XH    0        // x hi frags  [16kt][4mt][32][uint4] = 32768
#define SM_XL    32768
#define SM_H1H   65536    // h1 hi frags [32kt][4mt][...] = 65536 (h2 aliases kt0-15)
#define SM_H1L   131072
#define SM_GATES 196608   // [64][16] f32
#define SM_YACC  200704   // [64] f32
#define SMEM_BYTES 200960

__device__ __forceinline__ void mma_bf16(float* d, const uint4& a, const uint2& b) {
    asm volatile(
        "mma.sync.aligned.m16n8k16.row.col.f32.bf16.bf16.f32 "
        "{%0,%1,%2,%3}, {%4,%5,%6,%7}, {%8,%9}, {%0,%1,%2,%3};"
        : "+f"(d[0]), "+f"(d[1]), "+f"(d[2]), "+f"(d[3])
        : "r"(a.x), "r"(a.y), "r"(a.z), "r"(a.w), "r"(b.x), "r"(b.y));
}

__device__ __forceinline__ void split2(float a, float b, u32& hi, u32& lo) {
    __nv_bfloat16 ha = __float2bfloat16(a), hb = __float2bfloat16(b);
    float ra = a - __bfloat162float(ha), rb = b - __bfloat162float(hb);
    __nv_bfloat16 la = __float2bfloat16(ra), lb = __float2bfloat16(rb);
    hi = (u32)__bfloat16_as_ushort(ha) | ((u32)__bfloat16_as_ushort(hb) << 16);
    lo = (u32)__bfloat16_as_ushort(la) | ((u32)__bfloat16_as_ushort(lb) << 16);
}

// ---------------- weight fragment converter ----------------
__global__ void convert_weights_kernel(const float* __restrict__ W1,
                                       const float* __restrict__ W2,
                                       const float* __restrict__ W3) {
    const u32 N1 = 16u * 16 * 64 * 2 * 32 * 2;   // 2,097,152
    const u32 N2 = 16u * 32 * 32 * 2 * 32 * 2;   // 2,097,152
    const u32 N3 = 16u * 16 * 8 * 2 * 32 * 2;    //   262,144
    u32 i = blockIdx.x * blockDim.x + threadIdx.x;
    const float* src; u32* dst; u32 idx, K, Nn;
    if (i < N1)            { src = W1; dst = g_w1p; idx = i;            K = 256; Nn = 512; }
    else if (i < N1 + N2)  { src = W2; dst = g_w2p; idx = i - N1;       K = 512; Nn = 256; }
    else if (i < N1+N2+N3) { src = W3; dst = g_w3p; idx = i - N1 - N2;  K = 256; Nn = 64;  }
    else return;

    u32 word = idx & 1, lane = (idx >> 1) & 31, part = (idx >> 6) & 1;
    u32 rest = idx >> 7;                      // [e][kt][nt]
    u32 ntc = Nn / 8;
    u32 nt = rest % ntc; rest /= ntc;
    u32 ktc = K / 16;
    u32 kt = rest % ktc; u32 e = rest / ktc;

    u32 n  = nt * 8 + (lane >> 2);
    u32 k0 = kt * 16 + (lane & 3) * 2 + word * 8;
    float v0 = src[((size_t)e * K + k0)     * Nn + n];
    float v1 = src[((size_t)e * K + k0 + 1) * Nn + n];
    u32 hi, lo;
    split2(v0, v1, hi, lo);
    dst[idx] = part ? lo : hi;
}

// ---------------- main fused kernel ----------------
__global__ __launch_bounds__(NT, 1)
void moe_yts_mma_kernel(const float* __restrict__ x,
                        const float* __restrict__ gate_w,
                        const float* __restrict__ gate_b,
                        const float* __restrict__ b1,
                        const float* __restrict__ b2,
                        const float* __restrict__ b3,
                        const float* __restrict__ head_w,
                        const float* __restrict__ head_b,
                        float* __restrict__ out)
{
    extern __shared__ char smem[];
    const int t  = threadIdx.x;
    const int w  = t >> 5, l = t & 31;
    const int mt = w & 3, wn = w >> 2;        // warp grid 4(m) x 2(n)
    const int g  = l >> 2, q = l & 3;
    const int b_base = blockIdx.x * MT;

    float* gates = (float*)(smem + SM_GATES);
    float* yacc  = (float*)(smem + SM_YACC);

    // ---- gate logits: thread -> (row = t>>2, experts (t&3)*4..+3) ----
    {
        int r = t >> 2, e0 = (t & 3) * 4;
        float a0 = gate_b[e0], a1 = gate_b[e0+1], a2 = gate_b[e0+2], a3 = gate_b[e0+3];
        const float* xr = x + (size_t)(b_base + r) * D_;
        for (int d = 0; d < D_; d++) {
            float xv = xr[d];
            float4 gw = *(const float4*)(gate_w + d * E_ + e0);
            a0 = fmaf(xv, gw.x, a0); a1 = fmaf(xv, gw.y, a1);
            a2 = fmaf(xv, gw.z, a2); a3 = fmaf(xv, gw.w, a3);
        }
        float* row = gates + r * E_ + e0;
        row[0] = a0; row[1] = a1; row[2] = a2; row[3] = a3;
    }

    // ---- x -> A-fragments (hi/lo) ----
    for (int idx = t; idx < MT * (D_ / 4); idx += NT) {
        int r = idx >> 6, c4 = idx & 63;
        float4 v = *(const float4*)(x + (size_t)(b_base + r) * D_ + c4 * 4);
        int kt = c4 >> 2, kk = (c4 & 3) * 4;
        int mtr = r >> 4, rr = r & 15, gg = rr & 7;
        int lane0 = gg * 4 + ((kk & 7) >> 1);
        int wsel = (kk >= 8 ? 2 : 0) + (rr >= 8 ? 1 : 0);
        u32 h0, l0, h1w, l1w;
        split2(v.x, v.y, h0, l0);
        split2(v.z, v.w, h1w, l1w);
        u32 off = (u32)((kt * 4 + mtr) * 512 + lane0 * 16 + wsel * 4);
        *(u32*)(smem + SM_XH + off)      = h0;
        *(u32*)(smem + SM_XH + off + 16) = h1w;
        *(u32*)(smem + SM_XL + off)      = l0;
        *(u32*)(smem + SM_XL + off + 16) = l1w;
    }
    __syncthreads();

    // ---- softmax rows + zero yacc ----
    if (t < MT) {
        float* row = gates + t * E_;
        float m = row[0];
        #pragma unroll
        for (int j = 1; j < E_; j++) m = fmaxf(m, row[j]);
        float s = 0.f;
        #pragma unroll
        for (int j = 0; j < E_; j++) { float v = expf(row[j] - m); row[j] = v; s += v; }
        float inv = 1.0f / s;
        #pragma unroll
        for (int j = 0; j < E_; j++) row[j] *= inv;
        yacc[t] = 0.f;
    }
    __syncthreads();

    for (int e = 0; e < E_; e++) {
        // ======== GEMM1: two N-halves of 256 ========
        #pragma unroll 1
        for (int h = 0; h < 2; h++) {
            float acc[16][4];
            #pragma unroll
            for (int j = 0; j < 16; j++)
                #pragma unroll
                for (int c = 0; c < 4; c++) acc[j][c] = 0.f;

            const char* wb = (const char*)g_w1p + (size_t)e * 524288
                           + (size_t)(h * 32 + wn * 16) * 512;
            #pragma unroll 1
            for (int kt = 0; kt < 16; kt++) {
                uint4 Ah = *(const uint4*)(smem + SM_XH + (kt * 4 + mt) * 512 + l * 16);
                uint4 Al = *(const uint4*)(smem + SM_XL + (kt * 4 + mt) * 512 + l * 16);
                const char* bk = wb + (size_t)kt * 32768;
                #pragma unroll
                for (int j = 0; j < 16; j++) {
                    uint2 Bh = *(const uint2*)(bk + j * 512 + l * 8);
                    uint2 Bl = *(const uint2*)(bk + j * 512 + 256 + l * 8);
                    mma_bf16(acc[j], Ah, Bh);
                    mma_bf16(acc[j], Ah, Bl);
                    mma_bf16(acc[j], Al, Bh);
                }
            }
            // epilogue: relu+bias, split, pack as A-frags for GEMM2
            int bn = h * 256 + wn * 128;
            #pragma unroll
            for (int jj = 0; jj < 8; jj++) {
                const float* bp = b1 + e * H1_ + bn + jj * 16;
                float b00 = bp[q * 2], b01 = bp[q * 2 + 1];
                float b10 = bp[8 + q * 2], b11 = bp[9 + q * 2];
                float r00 = fmaxf(acc[2*jj][0]   + b00, 0.f), r01 = fmaxf(acc[2*jj][1]   + b01, 0.f);
                float r02 = fmaxf(acc[2*jj][2]   + b00, 0.f), r03 = fmaxf(acc[2*jj][3]   + b01, 0.f);
                float r10 = fmaxf(acc[2*jj+1][0] + b10, 0.f), r11 = fmaxf(acc[2*jj+1][1] + b11, 0.f);
                float r12 = fmaxf(acc[2*jj+1][2] + b10, 0.f), r13 = fmaxf(acc[2*jj+1][3] + b11, 0.f);
                uint4 H, L;
                split2(r00, r01, H.x, L.x);
                split2(r02, r03, H.y, L.y);
                split2(r10, r11, H.z, L.z);
                split2(r12, r13, H.w, L.w);
                int ktp = h * 16 + wn * 8 + jj;
                *(uint4*)(smem + SM_H1H + (ktp * 4 + mt) * 512 + l * 16) = H;
                *(uint4*)(smem + SM_H1L + (ktp * 4 + mt) * 512 + l * 16) = L;
            }
        }
        __syncthreads();

        // ======== GEMM2: [64,512]@[512,256] ========
        {
            float acc[16][4];
            #pragma unroll
            for (int j = 0; j < 16; j++)
                #pragma unroll
                for (int c = 0; c < 4; c++) acc[j][c] = 0.f;

            const char* wb = (const char*)g_w2p + (size_t)e * 524288 + (size_t)(wn * 16) * 512;
            #pragma unroll 1
            for (int kt = 0; kt < 32; kt++) {
                uint4 Ah = *(const uint4*)(smem + SM_H1H + (kt * 4 + mt) * 512 + l * 16);
                uint4 Al = *(const uint4*)(smem + SM_H1L + (kt * 4 + mt) * 512 + l * 16);
                const char* bk = wb + (size_t)kt * 16384;
                #pragma unroll
                for (int j = 0; j < 16; j++) {
                    uint2 Bh = *(const uint2*)(bk + j * 512 + l * 8);
                    uint2 Bl = *(const uint2*)(bk + j * 512 + 256 + l * 8);
                    mma_bf16(acc[j], Ah, Bh);
                    mma_bf16(acc[j], Ah, Bl);
                    mma_bf16(acc[j], Al, Bh);
                }
            }
            __syncthreads();   // all reads of h1 done before aliasing write
            int bn = wn * 128;
            #pragma unroll
            for (int jj = 0; jj < 8; jj++) {
                const float* bp = b2 + e * H2_ + bn + jj * 16;
                float b00 = bp[q * 2], b01 = bp[q * 2 + 1];
                float b10 = bp[8 + q * 2], b11 = bp[9 + q * 2];
                float r00 = fmaxf(acc[2*jj][0]   + b00, 0.f), r01 = fmaxf(acc[2*jj][1]   + b01, 0.f);
                float r02 = fmaxf(acc[2*jj][2]   + b00, 0.f), r03 = fmaxf(acc[2*jj][3]   + b01, 0.f);
                float r10 = fmaxf(acc[2*jj+1][0] + b10, 0.f), r11 = fmaxf(acc[2*jj+1][1] + b11, 0.f);
                float r12 = fmaxf(acc[2*jj+1][2] + b10, 0.f), r13 = fmaxf(acc[2*jj+1][3] + b11, 0.f);
                uint4 H, L;
                split2(r00, r01, H.x, L.x);
                split2(r02, r03, H.y, L.y);
                split2(r10, r11, H.z, L.z);
                split2(r12, r13, H.w, L.w);
                int ktp = wn * 8 + jj;          // h2 frags alias H1 kt0..15
                *(uint4*)(smem + SM_H1H + (ktp * 4 + mt) * 512 + l * 16) = H;
                *(uint4*)(smem + SM_H1L + (ktp * 4 + mt) * 512 + l * 16) = L;
            }
        }
        __syncthreads();

        // ======== GEMM3: [64,256]@[256,64] + gated head ========
        {
            float acc[4][4];
            #pragma unroll
            for (int j = 0; j < 4; j++)
                #pragma unroll
                for (int c = 0; c < 4; c++) acc[j][c] = 0.f;

            const char* wb = (const char*)g_w3p + (size_t)e * 65536 + (size_t)(wn * 4) * 512;
            #pragma unroll 1
            for (int kt = 0; kt < 16; kt++) {
                uint4 Ah = *(const uint4*)(smem + SM_H1H + (kt * 4 + mt) * 512 + l * 16);
                uint4 Al = *(const uint4*)(smem + SM_H1L + (kt * 4 + mt) * 512 + l * 16);
                const char* bk = wb + (size_t)kt * 4096;
                #pragma unroll
                for (int j = 0; j < 4; j++) {
                    uint2 Bh = *(const uint2*)(bk + j * 512 + l * 8);
                    uint2 Bl = *(const uint2*)(bk + j * 512 + 256 + l * 8);
                    mma_bf16(acc[j], Ah, Bh);
                    mma_bf16(acc[j], Ah, Bl);
                    mma_bf16(acc[j], Al, Bh);
                }
            }
            float p0 = 0.f, p8 = 0.f;
            #pragma unroll
            for (int j = 0; j < 4; j++) {
                int o = wn * 32 + j * 8 + q * 2;
                float hw0 = head_w[o], hw1 = head_w[o + 1];
                float b30 = b3[e * O_ + o], b31 = b3[e * O_ + o + 1];
                p0 += (acc[j][0] + b30) * hw0 + (acc[j][1] + b31) * hw1;
                p8 += (acc[j][2] + b30) * hw0 + (acc[j][3] + b31) * hw1;
            }
            p0 *= gates[(mt * 16 + g) * E_ + e];
            p8 *= gates[(mt * 16 + 8 + g) * E_ + e];
            p0 += __shfl_xor_sync(0xffffffffu, p0, 1);
            p0 += __shfl_xor_sync(0xffffffffu, p0, 2);
            p8 += __shfl_xor_sync(0xffffffffu, p8, 1);
            p8 += __shfl_xor_sync(0xffffffffu, p8, 2);
            if (q == 0) {
                atomicAdd(&yacc[mt * 16 + g], p0);
                atomicAdd(&yacc[mt * 16 + 8 + g], p8);
            }
        }
        __syncthreads();   // h2 region reusable; yacc consistent
    }

    if (t < MT)
        out[b_base + t] = yacc[t] + head_b[0];
}

extern "C" void kernel_launch(void* const* d_in, const int* in_sizes, int n_in,
                              void* d_out, int out_size) {
    const float* x      = (const float*)d_in[0];
    const float* gate_w = (const float*)d_in[1];
    const float* gate_b = (const float*)d_in[2];
    const float* W1     = (const float*)d_in[3];
    const float* b1     = (const float*)d_in[4];
    const float* W2     = (const float*)d_in[5];
    const float* b2     = (const float*)d_in[6];
    const float* W3     = (const float*)d_in[7];
    const float* b3     = (const float*)d_in[8];
    const float* head_w = (const float*)d_in[9];
    const float* head_b = (const float*)d_in[10];
    float* out = (float*)d_out;

    const u32 total_words = 16u*16*64*2*32*2 + 16u*32*32*2*32*2 + 16u*16*8*2*32*2;
    convert_weights_kernel<<<(total_words + 255) / 256, 256>>>(W1, W2, W3);

    cudaFuncSetAttribute(moe_yts_mma_kernel,
                         cudaFuncAttributeMaxDynamicSharedMemorySize, SMEM_BYTES);
    moe_yts_mma_kernel<<<B_ / MT, NT, SMEM_BYTES>>>(
        x, gate_w, gate_b, b1, b2, b3, head_w, head_b, out);
}

// round 8
// speedup vs baseline: 3.6628x; 1.1777x over previous
#include <cuda_runtime.h>
#include <cuda_bf16.h>
#include <cstdint>

typedef uint32_t u32;
typedef uint64_t u64;

#define D_  256
#define H1_ 512
#define H2_ 256
#define E_  16
#define O_  64
#define B_  32768
#define MT  64          // batch rows per CTA
#define NT  512         // threads (16 warps: 4m x 4n)

// ---------- fragment-packed weight buffers ----------
// layout: [e][kt][nt][part(hi,lo)][lane(32)][word(2)] u32
__device__ u32 g_w1p[16u * 16 * 64 * 2 * 32 * 2];   // 2,097,152 u32
__device__ u32 g_w2p[16u * 32 * 32 * 2 * 32 * 2];   // 2,097,152 u32
__device__ u32 g_w3p[16u * 16 * 8 * 2 * 32 * 2];    //   262,144 u32

// ---------- SMEM (bytes) ----------
#define SM_XH    0        // x hi frags  [16kt][4mt][32][16B] = 32768
#define SM_XL    32768
#define SM_H1H   65536    // h1 hi frags [32kt][4mt][...] = 65536 (h2 aliases kt0-15)
#define SM_H1L   131072
#define SM_GATES 196608   // [64][16] f32
#define SM_YACC  200704   // [64] f32
#define SMEM_BYTES 200960

__device__ __forceinline__ void mma_bf16(float* d, const uint4& a, const uint2& b) {
    asm volatile(
        "mma.sync.aligned.m16n8k16.row.col.f32.bf16.bf16.f32 "
        "{%0,%1,%2,%3}, {%4,%5,%6,%7}, {%8,%9}, {%0,%1,%2,%3};"
        : "+f"(d[0]), "+f"(d[1]), "+f"(d[2]), "+f"(d[3])
        : "r"(a.x), "r"(a.y), "r"(a.z), "r"(a.w), "r"(b.x), "r"(b.y));
}

__device__ __forceinline__ void split2(float a, float b, u32& hi, u32& lo) {
    __nv_bfloat16 ha = __float2bfloat16(a), hb = __float2bfloat16(b);
    float ra = a - __bfloat162float(ha), rb = b - __bfloat162float(hb);
    __nv_bfloat16 la = __float2bfloat16(ra), lb = __float2bfloat16(rb);
    hi = (u32)__bfloat16_as_ushort(ha) | ((u32)__bfloat16_as_ushort(hb) << 16);
    lo = (u32)__bfloat16_as_ushort(la) | ((u32)__bfloat16_as_ushort(lb) << 16);
}

// ---------------- weight fragment converter (unchanged, verified) ------------
__global__ void convert_weights_kernel(const float* __restrict__ W1,
                                       const float* __restrict__ W2,
                                       const float* __restrict__ W3) {
    const u32 N1 = 16u * 16 * 64 * 2 * 32 * 2;
    const u32 N2 = 16u * 32 * 32 * 2 * 32 * 2;
    const u32 N3 = 16u * 16 * 8 * 2 * 32 * 2;
    u32 i = blockIdx.x * blockDim.x + threadIdx.x;
    const float* src; u32* dst; u32 idx, K, Nn;
    if (i < N1)            { src = W1; dst = g_w1p; idx = i;            K = 256; Nn = 512; }
    else if (i < N1 + N2)  { src = W2; dst = g_w2p; idx = i - N1;       K = 512; Nn = 256; }
    else if (i < N1+N2+N3) { src = W3; dst = g_w3p; idx = i - N1 - N2;  K = 256; Nn = 64;  }
    else return;

    u32 word = idx & 1, lane = (idx >> 1) & 31, part = (idx >> 6) & 1;
    u32 rest = idx >> 7;
    u32 ntc = Nn / 8;
    u32 nt = rest % ntc; rest /= ntc;
    u32 ktc = K / 16;
    u32 kt = rest % ktc; u32 e = rest / ktc;

    u32 n  = nt * 8 + (lane >> 2);
    u32 k0 = kt * 16 + (lane & 3) * 2 + word * 8;
    float v0 = src[((size_t)e * K + k0)     * Nn + n];
    float v1 = src[((size_t)e * K + k0 + 1) * Nn + n];
    u32 hi, lo;
    split2(v0, v1, hi, lo);
    dst[idx] = part ? lo : hi;
}

// inner tile: batch-load 2*NJ B-frags, then term-grouped MMAs (no RAW chains)
template<int NJ>
__device__ __forceinline__ void mma_tile(float acc[][4], const uint4& Ah, const uint4& Al,
                                         const char* bk) {
    uint2 Bh[NJ], Bl[NJ];
    #pragma unroll
    for (int j = 0; j < NJ; j++) {
        Bh[j] = *(const uint2*)(bk + j * 512 + (threadIdx.x & 31) * 8);
        Bl[j] = *(const uint2*)(bk + j * 512 + 256 + (threadIdx.x & 31) * 8);
    }
    #pragma unroll
    for (int j = 0; j < NJ; j++) mma_bf16(acc[j], Ah, Bh[j]);
    #pragma unroll
    for (int j = 0; j < NJ; j++) mma_bf16(acc[j], Ah, Bl[j]);
    #pragma unroll
    for (int j = 0; j < NJ; j++) mma_bf16(acc[j], Al, Bh[j]);
}

// ---------------- main fused kernel ----------------
__global__ __launch_bounds__(NT, 1)
void moe_yts_mma_kernel(const float* __restrict__ x,
                        const float* __restrict__ gate_w,
                        const float* __restrict__ gate_b,
                        const float* __restrict__ b1,
                        const float* __restrict__ b2,
                        const float* __restrict__ b3,
                        const float* __restrict__ head_w,
                        const float* __restrict__ head_b,
                        float* __restrict__ out)
{
    extern __shared__ char smem[];
    const int t  = threadIdx.x;
    const int w  = t >> 5, l = t & 31;
    const int mt = w & 3, wn = w >> 2;        // warp grid 4(m) x 4(n)
    const int g  = l >> 2, q = l & 3;
    const int b_base = blockIdx.x * MT;

    float* gates = (float*)(smem + SM_GATES);
    float* yacc  = (float*)(smem + SM_YACC);

    // ---- gate logits: thread -> (row = t>>3, experts (t&7)*2..+1) ----
    {
        int r = t >> 3, e0 = (t & 7) * 2;
        float a0 = gate_b[e0], a1 = gate_b[e0 + 1];
        const float* xr = x + (size_t)(b_base + r) * D_;
        for (int d = 0; d < D_; d++) {
            float xv = xr[d];
            float2 gw = *(const float2*)(gate_w + d * E_ + e0);
            a0 = fmaf(xv, gw.x, a0); a1 = fmaf(xv, gw.y, a1);
        }
        gates[r * E_ + e0] = a0; gates[r * E_ + e0 + 1] = a1;
    }

    // ---- x -> A-fragments (hi/lo) ----
    for (int idx = t; idx < MT * (D_ / 4); idx += NT) {
        int r = idx >> 6, c4 = idx & 63;
        float4 v = *(const float4*)(x + (size_t)(b_base + r) * D_ + c4 * 4);
        int kt = c4 >> 2, kk = (c4 & 3) * 4;
        int mtr = r >> 4, rr = r & 15, gg = rr & 7;
        int lane0 = gg * 4 + ((kk & 7) >> 1);
        int wsel = (kk >= 8 ? 2 : 0) + (rr >= 8 ? 1 : 0);
        u32 h0, l0, h1w, l1w;
        split2(v.x, v.y, h0, l0);
        split2(v.z, v.w, h1w, l1w);
        u32 off = (u32)((kt * 4 + mtr) * 512 + lane0 * 16 + wsel * 4);
        *(u32*)(smem + SM_XH + off)      = h0;
        *(u32*)(smem + SM_XH + off + 16) = h1w;
        *(u32*)(smem + SM_XL + off)      = l0;
        *(u32*)(smem + SM_XL + off + 16) = l1w;
    }
    __syncthreads();

    // ---- softmax rows + zero yacc ----
    if (t < MT) {
        float* row = gates + t * E_;
        float m = row[0];
        #pragma unroll
        for (int j = 1; j < E_; j++) m = fmaxf(m, row[j]);
        float s = 0.f;
        #pragma unroll
        for (int j = 0; j < E_; j++) { float v = expf(row[j] - m); row[j] = v; s += v; }
        float inv = 1.0f / s;
        #pragma unroll
        for (int j = 0; j < E_; j++) row[j] *= inv;
        yacc[t] = 0.f;
    }
    __syncthreads();

    for (int e = 0; e < E_; e++) {
        // ======== GEMM1: [64,256]@[256,512], per warp 128 cols in 2 subpasses ====
        #pragma unroll 1
        for (int sub = 0; sub < 2; sub++) {
            float acc[8][4];
            #pragma unroll
            for (int j = 0; j < 8; j++)
                #pragma unroll
                for (int c = 0; c < 4; c++) acc[j][c] = 0.f;

            const char* wb = (const char*)g_w1p + (size_t)e * 524288
                           + (size_t)(wn * 16 + sub * 8) * 512;
            #pragma unroll 1
            for (int kt = 0; kt < 16; kt++) {
                uint4 Ah = *(const uint4*)(smem + SM_XH + (kt * 4 + mt) * 512 + l * 16);
                uint4 Al = *(const uint4*)(smem + SM_XL + (kt * 4 + mt) * 512 + l * 16);
                mma_tile<8>(acc, Ah, Al, wb + (size_t)kt * 32768);
            }
            int bn = wn * 128 + sub * 64;
            #pragma unroll
            for (int jj = 0; jj < 4; jj++) {
                const float* bp = b1 + e * H1_ + bn + jj * 16;
                float b00 = bp[q * 2], b01 = bp[q * 2 + 1];
                float b10 = bp[8 + q * 2], b11 = bp[9 + q * 2];
                float r00 = fmaxf(acc[2*jj][0]   + b00, 0.f), r01 = fmaxf(acc[2*jj][1]   + b01, 0.f);
                float r02 = fmaxf(acc[2*jj][2]   + b00, 0.f), r03 = fmaxf(acc[2*jj][3]   + b01, 0.f);
                float r10 = fmaxf(acc[2*jj+1][0] + b10, 0.f), r11 = fmaxf(acc[2*jj+1][1] + b11, 0.f);
                float r12 = fmaxf(acc[2*jj+1][2] + b10, 0.f), r13 = fmaxf(acc[2*jj+1][3] + b11, 0.f);
                uint4 H, L;
                split2(r00, r01, H.x, L.x);
                split2(r02, r03, H.y, L.y);
                split2(r10, r11, H.z, L.z);
                split2(r12, r13, H.w, L.w);
                int ktp = wn * 8 + sub * 4 + jj;
                *(uint4*)(smem + SM_H1H + (ktp * 4 + mt) * 512 + l * 16) = H;
                *(uint4*)(smem + SM_H1L + (ktp * 4 + mt) * 512 + l * 16) = L;
            }
        }
        __syncthreads();

        // ======== GEMM2: [64,512]@[512,256], per warp 64 cols ========
        {
            float acc[8][4];
            #pragma unroll
            for (int j = 0; j < 8; j++)
                #pragma unroll
                for (int c = 0; c < 4; c++) acc[j][c] = 0.f;

            const char* wb = (const char*)g_w2p + (size_t)e * 524288 + (size_t)(wn * 8) * 512;
            #pragma unroll 1
            for (int kt = 0; kt < 32; kt++) {
                uint4 Ah = *(const uint4*)(smem + SM_H1H + (kt * 4 + mt) * 512 + l * 16);
                uint4 Al = *(const uint4*)(smem + SM_H1L + (kt * 4 + mt) * 512 + l * 16);
                mma_tile<8>(acc, Ah, Al, wb + (size_t)kt * 16384);
            }
            __syncthreads();   // all reads of h1 done before aliasing write
            int bn = wn * 64;
            #pragma unroll
            for (int jj = 0; jj < 4; jj++) {
                const float* bp = b2 + e * H2_ + bn + jj * 16;
                float b00 = bp[q * 2], b01 = bp[q * 2 + 1];
                float b10 = bp[8 + q * 2], b11 = bp[9 + q * 2];
                float r00 = fmaxf(acc[2*jj][0]   + b00, 0.f), r01 = fmaxf(acc[2*jj][1]   + b01, 0.f);
                float r02 = fmaxf(acc[2*jj][2]   + b00, 0.f), r03 = fmaxf(acc[2*jj][3]   + b01, 0.f);
                float r10 = fmaxf(acc[2*jj+1][0] + b10, 0.f), r11 = fmaxf(acc[2*jj+1][1] + b11, 0.f);
                float r12 = fmaxf(acc[2*jj+1][2] + b10, 0.f), r13 = fmaxf(acc[2*jj+1][3] + b11, 0.f);
                uint4 H, L;
                split2(r00, r01, H.x, L.x);
                split2(r02, r03, H.y, L.y);
                split2(r10, r11, H.z, L.z);
                split2(r12, r13, H.w, L.w);
                int ktp = wn * 4 + jj;          // h2 frags alias H1 kt0..15
                *(uint4*)(smem + SM_H1H + (ktp * 4 + mt) * 512 + l * 16) = H;
                *(uint4*)(smem + SM_H1L + (ktp * 4 + mt) * 512 + l * 16) = L;
            }
        }
        __syncthreads();

        // ======== GEMM3: [64,256]@[256,64], per warp 16 cols + gated head ========
        {
            float acc[2][4];
            #pragma unroll
            for (int j = 0; j < 2; j++)
                #pragma unroll
                for (int c = 0; c < 4; c++) acc[j][c] = 0.f;

            const char* wb = (const char*)g_w3p + (size_t)e * 65536 + (size_t)(wn * 2) * 512;
            #pragma unroll 1
            for (int kt = 0; kt < 16; kt++) {
                uint4 Ah = *(const uint4*)(smem + SM_H1H + (kt * 4 + mt) * 512 + l * 16);
                uint4 Al = *(const uint4*)(smem + SM_H1L + (kt * 4 + mt) * 512 + l * 16);
                mma_tile<2>(acc, Ah, Al, wb + (size_t)kt * 4096);
            }
            float p0 = 0.f, p8 = 0.f;
            #pragma unroll
            for (int j = 0; j < 2; j++) {
                int o = wn * 16 + j * 8 + q * 2;
                float hw0 = head_w[o], hw1 = head_w[o + 1];
                float b30 = b3[e * O_ + o], b31 = b3[e * O_ + o + 1];
                p0 += (acc[j][0] + b30) * hw0 + (acc[j][1] + b31) * hw1;
                p8 += (acc[j][2] + b30) * hw0 + (acc[j][3] + b31) * hw1;
            }
            p0 *= gates[(mt * 16 + g) * E_ + e];
            p8 *= gates[(mt * 16 + 8 + g) * E_ + e];
            p0 += __shfl_xor_sync(0xffffffffu, p0, 1);
            p0 += __shfl_xor_sync(0xffffffffu, p0, 2);
            p8 += __shfl_xor_sync(0xffffffffu, p8, 1);
            p8 += __shfl_xor_sync(0xffffffffu, p8, 2);
            if (q == 0) {
                atomicAdd(&yacc[mt * 16 + g], p0);
                atomicAdd(&yacc[mt * 16 + 8 + g], p8);
            }
        }
        __syncthreads();   // h2 region reusable; yacc consistent
    }

    if (t < MT)
        out[b_base + t] = yacc[t] + head_b[0];
}

extern "C" void kernel_launch(void* const* d_in, const int* in_sizes, int n_in,
                              void* d_out, int out_size) {
    const float* x      = (const float*)d_in[0];
    const float* gate_w = (const float*)d_in[1];
    const float* gate_b = (const float*)d_in[2];
    const float* W1     = (const float*)d_in[3];
    const float* b1     = (const float*)d_in[4];
    const float* W2     = (const float*)d_in[5];
    const float* b2     = (const float*)d_in[6];
    const float* W3     = (const float*)d_in[7];
    const float* b3     = (const float*)d_in[8];
    const float* head_w = (const float*)d_in[9];
    const float* head_b = (const float*)d_in[10];
    float* out = (float*)d_out;

    const u32 total_words = 16u*16*64*2*32*2 + 16u*32*32*2*32*2 + 16u*16*8*2*32*2;
    convert_weights_kernel<<<(total_words + 255) / 256, 256>>>(W1, W2, W3);

    cudaFuncSetAttribute(moe_yts_mma_kernel,
                         cudaFuncAttributeMaxDynamicSharedMemorySize, SMEM_BYTES);
    moe_yts_mma_kernel<<<B_ / MT, NT, SMEM_BYTES>>>(
        x, gate_w, gate_b, b1, b2, b3, head_w, head_b, out);
}

// round 11
// speedup vs baseline: 3.9006x; 1.0649x over previous
#include <cuda_runtime.h>
#include <cuda_bf16.h>
#include <cstdint>

typedef uint32_t u32;
typedef uint64_t u64;

#define D_  256
#define H1_ 512
#define H2_ 256
#define E_  16
#define O_  64
#define B_  32768
#define MT  64          // batch rows per CTA
#define NT  512         // threads (16 warps: 4m x 4n)

// ---------- fragment-packed weight buffers ----------
// layout: [e][kt][nt][lane(32)][w4] u32 where w4 = {h.w0, h.w1, l.w0, l.w1}
__device__ u32 g_w1p[16u * 16 * 64 * 32 * 4];   // 2,097,152 u32
__device__ u32 g_w2p[16u * 32 * 32 * 32 * 4];   // 2,097,152 u32
__device__ u32 g_w3p[16u * 16 * 8 * 32 * 4];    //   262,144 u32

// per-expert byte strides (tile bytes)
#define W1_EB 524288u   // 16kt * 64nt * 512B
#define W2_EB 524288u   // 32kt * 32nt * 512B
#define W3_EB 65536u    // 16kt *  8nt * 512B

// ---------- SMEM (bytes) ----------
#define SM_XH    0        // x hi frags  [16kt][4mt][32][16B] = 32768
#define SM_XL    32768
#define SM_H1H   65536    // h1 hi frags [32kt][4mt][...] = 65536 (h2 aliases kt0-15)
#define SM_H1L   131072
#define SM_GATES 196608   // [64][16] f32
#define SM_YACC  200704   // [64] f32
#define SMEM_BYTES 200960

__device__ __forceinline__ void mma_bf16(float* d, const uint4& a, u32 b0, u32 b1) {
    asm volatile(
        "mma.sync.aligned.m16n8k16.row.col.f32.bf16.bf16.f32 "
        "{%0,%1,%2,%3}, {%4,%5,%6,%7}, {%8,%9}, {%0,%1,%2,%3};"
        : "+f"(d[0]), "+f"(d[1]), "+f"(d[2]), "+f"(d[3])
        : "r"(a.x), "r"(a.y), "r"(a.z), "r"(a.w), "r"(b0), "r"(b1));
}

__device__ __forceinline__ void split2(float a, float b, u32& hi, u32& lo) {
    __nv_bfloat16 ha = __float2bfloat16(a), hb = __float2bfloat16(b);
    float ra = a - __bfloat162float(ha), rb = b - __bfloat162float(hb);
    __nv_bfloat16 la = __float2bfloat16(ra), lb = __float2bfloat16(rb);
    hi = (u32)__bfloat16_as_ushort(ha) | ((u32)__bfloat16_as_ushort(hb) << 16);
    lo = (u32)__bfloat16_as_ushort(la) | ((u32)__bfloat16_as_ushort(lb) << 16);
}

// ---------------- weight fragment converter ----------------
__global__ void convert_weights_kernel(const float* __restrict__ W1,
                                       const float* __restrict__ W2,
                                       const float* __restrict__ W3) {
    const u32 N1 = 16u * 16 * 64 * 32 * 4;
    const u32 N2 = 16u * 32 * 32 * 32 * 4;
    const u32 N3 = 16u * 16 * 8 * 32 * 4;
    u32 i = blockIdx.x * blockDim.x + threadIdx.x;
    const float* src; u32* dst; u32 idx, K, Nn;
    if (i < N1)            { src = W1; dst = g_w1p; idx = i;            K = 256; Nn = 512; }
    else if (i < N1 + N2)  { src = W2; dst = g_w2p; idx = i - N1;       K = 512; Nn = 256; }
    else if (i < N1+N2+N3) { src = W3; dst = g_w3p; idx = i - N1 - N2;  K = 256; Nn = 64;  }
    else return;

    u32 w4 = idx & 3;                // {h.w0, h.w1, l.w0, l.w1}
    u32 word = w4 & 1, part = w4 >> 1;
    u32 lane = (idx >> 2) & 31;
    u32 rest = idx >> 7;             // [e][kt][nt]
    u32 ntc = Nn / 8;
    u32 nt = rest % ntc; rest /= ntc;
    u32 ktc = K / 16;
    u32 kt = rest % ktc; u32 e = rest / ktc;

    u32 n  = nt * 8 + (lane >> 2);
    u32 k0 = kt * 16 + (lane & 3) * 2 + word * 8;
    float v0 = src[((size_t)e * K + k0)     * Nn + n];
    float v1 = src[((size_t)e * K + k0 + 1) * Nn + n];
    u32 hi, lo;
    split2(v0, v1, hi, lo);
    dst[idx] = part ? lo : hi;
}

template<int NJ>
__device__ __forceinline__ void load_B(uint4* B, const char* bk, int l) {
    #pragma unroll
    for (int j = 0; j < NJ; j++)
        B[j] = *(const uint4*)(bk + j * 512 + l * 16);
}

// term-grouped MMAs (no accumulator RAW chains); B[j] = {Bh0,Bh1,Bl0,Bl1}
template<int NJ>
__device__ __forceinline__ void mma_terms(float acc[][4], const uint4& Ah, const uint4& Al,
                                          const uint4* B) {
    #pragma unroll
    for (int j = 0; j < NJ; j++) mma_bf16(acc[j], Ah, B[j].x, B[j].y);
    #pragma unroll
    for (int j = 0; j < NJ; j++) mma_bf16(acc[j], Ah, B[j].z, B[j].w);
    #pragma unroll
    for (int j = 0; j < NJ; j++) mma_bf16(acc[j], Al, B[j].x, B[j].y);
}

// ---------------- main fused kernel ----------------
__global__ __launch_bounds__(NT, 1)
void moe_yts_mma_kernel(const float* __restrict__ x,
                        const float* __restrict__ gate_w,
                        const float* __restrict__ gate_b,
                        const float* __restrict__ b1,
                        const float* __restrict__ b2,
                        const float* __restrict__ b3,
                        const float* __restrict__ head_w,
                        const float* __restrict__ head_b,
                        float* __restrict__ out)
{
    extern __shared__ char smem[];
    const int t  = threadIdx.x;
    const int w  = t >> 5, l = t & 31;
    const int mt = w & 3, wn = w >> 2;        // warp grid 4(m) x 4(n)
    const int g  = l >> 2, q = l & 3;
    const int b_base = blockIdx.x * MT;

    float* gates = (float*)(smem + SM_GATES);
    float* yacc  = (float*)(smem + SM_YACC);

    // ---- gate logits ----
    {
        int r = t >> 3, e0 = (t & 7) * 2;
        float a0 = gate_b[e0], a1 = gate_b[e0 + 1];
        const float* xr = x + (size_t)(b_base + r) * D_;
        for (int d = 0; d < D_; d++) {
            float xv = xr[d];
            float2 gw = *(const float2*)(gate_w + d * E_ + e0);
            a0 = fmaf(xv, gw.x, a0); a1 = fmaf(xv, gw.y, a1);
        }
        gates[r * E_ + e0] = a0; gates[r * E_ + e0 + 1] = a1;
    }

    // ---- x -> A-fragments (hi/lo) ----
    for (int idx = t; idx < MT * (D_ / 4); idx += NT) {
        int r = idx >> 6, c4 = idx & 63;
        float4 v = *(const float4*)(x + (size_t)(b_base + r) * D_ + c4 * 4);
        int kt = c4 >> 2, kk = (c4 & 3) * 4;
        int mtr = r >> 4, rr = r & 15, gg = rr & 7;
        int lane0 = gg * 4 + ((kk & 7) >> 1);
        int wsel = (kk >= 8 ? 2 : 0) + (rr >= 8 ? 1 : 0);
        u32 h0, l0, h1w, l1w;
        split2(v.x, v.y, h0, l0);
        split2(v.z, v.w, h1w, l1w);
        u32 off = (u32)((kt * 4 + mtr) * 512 + lane0 * 16 + wsel * 4);
        *(u32*)(smem + SM_XH + off)      = h0;
        *(u32*)(smem + SM_XH + off + 16) = h1w;
        *(u32*)(smem + SM_XL + off)      = l0;
        *(u32*)(smem + SM_XL + off + 16) = l1w;
    }
    __syncthreads();

    // ---- softmax rows + zero yacc ----
    if (t < MT) {
        float* row = gates + t * E_;
        float m = row[0];
        #pragma unroll
        for (int j = 1; j < E_; j++) m = fmaxf(m, row[j]);
        float s = 0.f;
        #pragma unroll
        for (int j = 0; j < E_; j++) { float v = expf(row[j] - m); row[j] = v; s += v; }
        float inv = 1.0f / s;
        #pragma unroll
        for (int j = 0; j < E_; j++) row[j] *= inv;
        yacc[t] = 0.f;
    }
    __syncthreads();

    for (int e = 0; e < E_; e++) {
        // ======== GEMM1: [64,256]@[256,512], per warp 128 cols in 2 subpasses ====
        #pragma unroll 1
        for (int sub = 0; sub < 2; sub++) {
            float acc[8][4];
            #pragma unroll
            for (int j = 0; j < 8; j++)
                #pragma unroll
                for (int c = 0; c < 4; c++) acc[j][c] = 0.f;

            const char* wb = (const char*)g_w1p + (size_t)e * W1_EB
                           + (size_t)(wn * 16 + sub * 8) * 512;
            uint4 Bb[2][8];
            load_B<8>(Bb[0], wb, l);
            #pragma unroll 2
            for (int kt = 0; kt < 16; kt++) {
                if (kt < 15)
                    load_B<8>(Bb[(kt + 1) & 1], wb + (size_t)(kt + 1) * 32768, l);
                uint4 Ah = *(const uint4*)(smem + SM_XH + (kt * 4 + mt) * 512 + l * 16);
                uint4 Al = *(const uint4*)(smem + SM_XL + (kt * 4 + mt) * 512 + l * 16);
                mma_terms<8>(acc, Ah, Al, Bb[kt & 1]);
            }
            int bn = wn * 128 + sub * 64;
            #pragma unroll
            for (int jj = 0; jj < 4; jj++) {
                const float* bp = b1 + e * H1_ + bn + jj * 16;
                float b00 = bp[q * 2], b01 = bp[q * 2 + 1];
                float b10 = bp[8 + q * 2], b11 = bp[9 + q * 2];
                float r00 = fmaxf(acc[2*jj][0]   + b00, 0.f), r01 = fmaxf(acc[2*jj][1]   + b01, 0.f);
                float r02 = fmaxf(acc[2*jj][2]   + b00, 0.f), r03 = fmaxf(acc[2*jj][3]   + b01, 0.f);
                float r10 = fmaxf(acc[2*jj+1][0] + b10, 0.f), r11 = fmaxf(acc[2*jj+1][1] + b11, 0.f);
                float r12 = fmaxf(acc[2*jj+1][2] + b10, 0.f), r13 = fmaxf(acc[2*jj+1][3] + b11, 0.f);
                uint4 H, L;
                split2(r00, r01, H.x, L.x);
                split2(r02, r03, H.y, L.y);
                split2(r10, r11, H.z, L.z);
                split2(r12, r13, H.w, L.w);
                int ktp = wn * 8 + sub * 4 + jj;
                *(uint4*)(smem + SM_H1H + (ktp * 4 + mt) * 512 + l * 16) = H;
                *(uint4*)(smem + SM_H1L + (ktp * 4 + mt) * 512 + l * 16) = L;
            }
        }
        __syncthreads();

        // ======== GEMM2: [64,512]@[512,256], per warp 64 cols ========
        {
            float acc[8][4];
            #pragma unroll
            for (int j = 0; j < 8; j++)
                #pragma unroll
                for (int c = 0; c < 4; c++) acc[j][c] = 0.f;

            const char* wb = (const char*)g_w2p + (size_t)e * W2_EB + (size_t)(wn * 8) * 512;
            uint4 Bb[2][8];
            load_B<8>(Bb[0], wb, l);
            #pragma unroll 2
            for (int kt = 0; kt < 32; kt++) {
                if (kt < 31)
                    load_B<8>(Bb[(kt + 1) & 1], wb + (size_t)(kt + 1) * 16384, l);
                uint4 Ah = *(const uint4*)(smem + SM_H1H + (kt * 4 + mt) * 512 + l * 16);
                uint4 Al = *(const uint4*)(smem + SM_H1L + (kt * 4 + mt) * 512 + l * 16);
                mma_terms<8>(acc, Ah, Al, Bb[kt & 1]);
            }
            __syncthreads();   // all reads of h1 done before aliasing write
            int bn = wn * 64;
            #pragma unroll
            for (int jj = 0; jj < 4; jj++) {
                const float* bp = b2 + e * H2_ + bn + jj * 16;
                float b00 = bp[q * 2], b01 = bp[q * 2 + 1];
                float b10 = bp[8 + q * 2], b11 = bp[9 + q * 2];
                float r00 = fmaxf(acc[2*jj][0]   + b00, 0.f), r01 = fmaxf(acc[2*jj][1]   + b01, 0.f);
                float r02 = fmaxf(acc[2*jj][2]   + b00, 0.f), r03 = fmaxf(acc[2*jj][3]   + b01, 0.f);
                float r10 = fmaxf(acc[2*jj+1][0] + b10, 0.f), r11 = fmaxf(acc[2*jj+1][1] + b11, 0.f);
                float r12 = fmaxf(acc[2*jj+1][2] + b10, 0.f), r13 = fmaxf(acc[2*jj+1][3] + b11, 0.f);
                uint4 H, L;
                split2(r00, r01, H.x, L.x);
                split2(r02, r03, H.y, L.y);
                split2(r10, r11, H.z, L.z);
                split2(r12, r13, H.w, L.w);
                int ktp = wn * 4 + jj;          // h2 frags alias H1 kt0..15
                *(uint4*)(smem + SM_H1H + (ktp * 4 + mt) * 512 + l * 16) = H;
                *(uint4*)(smem + SM_H1L + (ktp * 4 + mt) * 512 + l * 16) = L;
            }
        }
        __syncthreads();

        // ======== GEMM3: [64,256]@[256,64], per warp 16 cols + gated head ========
        {
            float acc[2][4];
            #pragma unroll
            for (int j = 0; j < 2; j++)
                #pragma unroll
                for (int c = 0; c < 4; c++) acc[j][c] = 0.f;

            const char* wb = (const char*)g_w3p + (size_t)e * W3_EB + (size_t)(wn * 2) * 512;
            uint4 Bb[2][2];
            load_B<2>(Bb[0], wb, l);
            #pragma unroll 2
            for (int kt = 0; kt < 16; kt++) {
                if (kt < 15)
                    load_B<2>(Bb[(kt + 1) & 1], wb + (size_t)(kt + 1) * 4096, l);
                uint4 Ah = *(const uint4*)(smem + SM_H1H + (kt * 4 + mt) * 512 + l * 16);
                uint4 Al = *(const uint4*)(smem + SM_H1L + (kt * 4 + mt) * 512 + l * 16);
                mma_terms<2>(acc, Ah, Al, Bb[kt & 1]);
            }
            float p0 = 0.f, p8 = 0.f;
            #pragma unroll
            for (int j = 0; j < 2; j++) {
                int o = wn * 16 + j * 8 + q * 2;
                float hw0 = head_w[o], hw1 = head_w[o + 1];
                float b30 = b3[e * O_ + o], b31 = b3[e * O_ + o + 1];
                p0 += (acc[j][0] + b30) * hw0 + (acc[j][1] + b31) * hw1;
                p8 += (acc[j][2] + b30) * hw0 + (acc[j][3] + b31) * hw1;
            }
            p0 *= gates[(mt * 16 + g) * E_ + e];
            p8 *= gates[(mt * 16 + 8 + g) * E_ + e];
            p0 += __shfl_xor_sync(0xffffffffu, p0, 1);
            p0 += __shfl_xor_sync(0xffffffffu, p0, 2);
            p8 += __shfl_xor_sync(0xffffffffu, p8, 1);
            p8 += __shfl_xor_sync(0xffffffffu, p8, 2);
            if (q == 0) {
                atomicAdd(&yacc[mt * 16 + g], p0);
                atomicAdd(&yacc[mt * 16 + 8 + g], p8);
            }
        }
        __syncthreads();   // h2 region reusable; yacc consistent
    }

    if (t < MT)
        out[b_base + t] = yacc[t] + head_b[0];
}

extern "C" void kernel_launch(void* const* d_in, const int* in_sizes, int n_in,
                              void* d_out, int out_size) {
    const float* x      = (const float*)d_in[0];
    const float* gate_w = (const float*)d_in[1];
    const float* gate_b = (const float*)d_in[2];
    const float* W1     = (const float*)d_in[3];
    const float* b1     = (const float*)d_in[4];
    const float* W2     = (const float*)d_in[5];
    const float* b2     = (const float*)d_in[6];
    const float* W3     = (const float*)d_in[7];
    const float* b3     = (const float*)d_in[8];
    const float* head_w = (const float*)d_in[9];
    const float* head_b = (const float*)d_in[10];
    float* out = (float*)d_out;

    const u32 total_words = 16u*16*64*32*4 + 16u*32*32*32*4 + 16u*16*8*32*4;
    convert_weights_kernel<<<(total_words + 255) / 256, 256>>>(W1, W2, W3);

    cudaFuncSetAttribute(moe_yts_mma_kernel,
                         cudaFuncAttributeMaxDynamicSharedMemorySize, SMEM_BYTES);
    moe_yts_mma_kernel<<<B_ / MT, NT, SMEM_BYTES>>>(
        x, gate_w, gate_b, b1, b2, b3, head_w, head_b, out);
}